// round 5
// baseline (speedup 1.0000x reference)
#include <cuda_runtime.h>
#include <cstdint>

#define N_NODES 100000
#define N_EDGES 500000
#define HIDDEN 32
#define HEADS 4
#define PROJ 128  // HIDDEN*HEADS
#define LN_EPS 1e-5f

// Scratch: node accumulator [N, 128] + per-node edge counts. 51.6 MB, fits L2.
__device__ float g_accum[(size_t)N_NODES * PROJ];
__device__ float g_cnt[N_NODES];
__device__ int   g_idx64;   // 1 if edge_index is int64, 0 if int32

// ---------------------------------------------------------------------------
// Kernel A: sniff edge_index dtype. If int64 (values < 2^31, >= 0), every odd
// 32-bit word is zero. 64 random int32 indices all being zero is impossible.
// ---------------------------------------------------------------------------
__global__ void sniff_kernel(const int* __restrict__ eidx32) {
    if (threadIdx.x == 0) {
        int all_zero = 1;
        for (int i = 0; i < 64; i++)
            if (eidx32[2 * i + 1] != 0) { all_zero = 0; break; }
        g_idx64 = all_zero;
    }
}

// ---------------------------------------------------------------------------
// Kernel 0: zero the scratch (graph replays require re-zeroing every launch)
// ---------------------------------------------------------------------------
__global__ __launch_bounds__(256) void zero_kernel() {
    const size_t n4 = ((size_t)N_NODES * PROJ) / 4;
    float4* a4 = reinterpret_cast<float4*>(g_accum);
    size_t stride = (size_t)gridDim.x * blockDim.x;
    for (size_t i = (size_t)blockIdx.x * blockDim.x + threadIdx.x; i < n4; i += stride)
        a4[i] = make_float4(0.f, 0.f, 0.f, 0.f);
    for (size_t i = (size_t)blockIdx.x * blockDim.x + threadIdx.x; i < N_NODES; i += stride)
        g_cnt[i] = 0.f;
}

// ---------------------------------------------------------------------------
// Kernel 1: per-(edge, head) attention + scatter-add.
// Thread t: edge = t>>2, head = t&3. Aligned 4-lane groups do the head
// softmax via shfl. Weights staged in smem.
// ---------------------------------------------------------------------------
__global__ __launch_bounds__(256) void edge_kernel(
    const float* __restrict__ pos,
    const void* __restrict__ eidx_raw,
    const float* __restrict__ Wq, const float* __restrict__ bq,
    const float* __restrict__ Wk, const float* __restrict__ bk,
    const float* __restrict__ Wv, const float* __restrict__ bv)
{
    __shared__ float sW[12 * PROJ];
    const int tid = threadIdx.x;
    for (int i = tid; i < 3 * PROJ; i += 256) {
        sW[i]            = Wq[i];
        sW[3 * PROJ + i] = Wk[i];
        sW[6 * PROJ + i] = Wv[i];
    }
    for (int i = tid; i < PROJ; i += 256) {
        sW[9 * PROJ + i]  = bq[i];
        sW[10 * PROJ + i] = bk[i];
        sW[11 * PROJ + i] = bv[i];
    }
    __syncthreads();

    const int gt = blockIdx.x * 256 + tid;
    if (gt >= N_EDGES * HEADS) return;
    const int e = gt >> 2;
    const int h = gt & 3;

    int row, col;
    if (g_idx64) {
        const long long* e64 = (const long long*)eidx_raw;
        row = (int)e64[e];
        col = (int)e64[N_EDGES + e];
    } else {
        const int* e32 = (const int*)eidx_raw;
        row = e32[e];
        col = e32[N_EDGES + e];
    }
    if ((unsigned)row >= N_NODES || (unsigned)col >= N_NODES) return;  // defensive

    const float rx = pos[row * 3 + 0] - pos[col * 3 + 0];
    const float ry = pos[row * 3 + 1] - pos[col * 3 + 1];
    const float rz = pos[row * 3 + 2] - pos[col * 3 + 2];

    const int c0 = h * 32;
    float v[32];
    float score = 0.f;
#pragma unroll
    for (int d = 0; d < 32; d++) {
        const int c = c0 + d;
        float q  = fmaf(rx, sW[c],          fmaf(ry, sW[PROJ + c],   fmaf(rz, sW[2*PROJ + c], sW[9*PROJ + c])));
        float k  = fmaf(rx, sW[3*PROJ + c], fmaf(ry, sW[4*PROJ + c], fmaf(rz, sW[5*PROJ + c], sW[10*PROJ + c])));
        float vv = fmaf(rx, sW[6*PROJ + c], fmaf(ry, sW[7*PROJ + c], fmaf(rz, sW[8*PROJ + c], sW[11*PROJ + c])));
        v[d] = vv;
        score = fmaf(q, k, score);
    }
    score *= 0.17677669529663687f;  // 1/sqrt(32)

    // softmax over the 4 heads of this edge (aligned 4-lane group)
    const unsigned gmask = 0xFu << (threadIdx.x & 28u);
    float m = score;
    m = fmaxf(m, __shfl_xor_sync(gmask, m, 1));
    m = fmaxf(m, __shfl_xor_sync(gmask, m, 2));
    const float ex = __expf(score - m);
    float s = ex;
    s += __shfl_xor_sync(gmask, s, 1);
    s += __shfl_xor_sync(gmask, s, 2);
    const float attn = ex / s;

    float* dst = g_accum + (size_t)col * PROJ + c0;
#pragma unroll
    for (int i = 0; i < 8; i++) {
        const float a0 = attn * v[4*i + 0];
        const float a1 = attn * v[4*i + 1];
        const float a2 = attn * v[4*i + 2];
        const float a3 = attn * v[4*i + 3];
        asm volatile("red.global.add.v4.f32 [%0], {%1,%2,%3,%4};"
                     :: "l"(dst + 4*i), "f"(a0), "f"(a1), "f"(a2), "f"(a3)
                     : "memory");
    }
    if (h == 0) atomicAdd(&g_cnt[col], 1.0f);
}

// ---------------------------------------------------------------------------
// Kernel 2: per-node mean, 128->32 matvec, LayerNorm, SiLU.
// One warp per node; lane j owns output dim j.
// ---------------------------------------------------------------------------
__global__ __launch_bounds__(256) void node_kernel(
    const float* __restrict__ Wout, const float* __restrict__ bout,
    const float* __restrict__ gamma, const float* __restrict__ beta,
    float* __restrict__ out)
{
    __shared__ float sWout[PROJ * HIDDEN];  // 16 KB
    __shared__ float sb[HIDDEN], sg[HIDDEN], sbt[HIDDEN];
    const int tid = threadIdx.x;
    for (int i = tid; i < PROJ * HIDDEN; i += 256) sWout[i] = Wout[i];
    if (tid < HIDDEN) { sb[tid] = bout[tid]; sg[tid] = gamma[tid]; sbt[tid] = beta[tid]; }
    __syncthreads();

    const int node = (blockIdx.x * 256 + tid) >> 5;
    const int lane = tid & 31;
    if (node >= N_NODES) return;

    const float* acc = g_accum + (size_t)node * PROJ;
    const float inv = 1.f / fmaxf(g_cnt[node], 1.f);

    float m[4];
#pragma unroll
    for (int r = 0; r < 4; r++) m[r] = acc[r * 32 + lane] * inv;

    float o = sb[lane];
#pragma unroll
    for (int r = 0; r < 4; r++) {
#pragma unroll
        for (int c = 0; c < 32; c++) {
            const float mv = __shfl_sync(0xFFFFFFFFu, m[r], c);
            o = fmaf(mv, sWout[(r * 32 + c) * HIDDEN + lane], o);
        }
    }

    float sum = o;
#pragma unroll
    for (int off = 16; off; off >>= 1) sum += __shfl_xor_sync(0xFFFFFFFFu, sum, off);
    const float mu = sum * (1.f / 32.f);
    const float d = o - mu;
    float sq = d * d;
#pragma unroll
    for (int off = 16; off; off >>= 1) sq += __shfl_xor_sync(0xFFFFFFFFu, sq, off);
    const float var = sq * (1.f / 32.f);
    const float y = d * rsqrtf(var + LN_EPS) * sg[lane] + sbt[lane];
    const float sig = 1.f / (1.f + __expf(-y));
    out[(size_t)node * HIDDEN + lane] = y * sig;
}

// ---------------------------------------------------------------------------
extern "C" void kernel_launch(void* const* d_in, const int* in_sizes, int n_in,
                              void* d_out, int out_size)
{
    const float* pos   = (const float*)d_in[0];
    const void*  eidx  = d_in[1];
    const float* Wq    = (const float*)d_in[2];
    const float* bq    = (const float*)d_in[3];
    const float* Wk    = (const float*)d_in[4];
    const float* bk    = (const float*)d_in[5];
    const float* Wv    = (const float*)d_in[6];
    const float* bv    = (const float*)d_in[7];
    const float* Wout  = (const float*)d_in[8];
    const float* bout  = (const float*)d_in[9];
    const float* gamma = (const float*)d_in[10];
    const float* beta  = (const float*)d_in[11];
    float*       out   = (float*)d_out;

    sniff_kernel<<<1, 32>>>((const int*)eidx);
    zero_kernel<<<1024, 256>>>();
    edge_kernel<<<(N_EDGES * HEADS + 255) / 256, 256>>>(pos, eidx, Wq, bq, Wk, bk, Wv, bv);
    node_kernel<<<(N_NODES * 32) / 256, 256>>>(Wout, bout, gamma, beta, out);
}

// round 6
// speedup vs baseline: 8.9549x; 8.9549x over previous
#include <cuda_runtime.h>
#include <cstdint>

#define N_NODES 100000
#define N_EDGES 500000
#define HIDDEN 32
#define HEADS 4
#define PROJ 128
#define LN_EPS 1e-5f

// Per-node accumulator: [node][head][{Sx,Sy,Sz,T}] = 16 floats = 64B. 6.4 MB, L2-hot.
__device__ float g_acc[(size_t)N_NODES * 16];
__device__ int   g_idx64;            // 1 if edge_index is int64
__device__ float g_PJ[HIDDEN * 16];  // folded Wv@Wout (+bv@Wout), layout [j][h*4+{x,y,z,T}]
__device__ float g_score[HEADS * 13];// per head: M[9] row-major, L[3], C

// ---------------------------------------------------------------------------
// dtype sniff: int64 indices (0 <= v < 2^31) have all-zero odd 32-bit words.
// ---------------------------------------------------------------------------
__global__ void sniff_kernel(const int* __restrict__ e32) {
    if (threadIdx.x == 0) {
        int all_zero = 1;
        for (int i = 0; i < 64; i++)
            if (e32[2 * i + 1] != 0) { all_zero = 0; break; }
        g_idx64 = all_zero;
    }
}

// ---------------------------------------------------------------------------
// Precompute folded coefficient tables (tiny; one block).
// ---------------------------------------------------------------------------
__global__ void precompute_kernel(
    const float* __restrict__ Wq, const float* __restrict__ bq,
    const float* __restrict__ Wk, const float* __restrict__ bk,
    const float* __restrict__ Wv, const float* __restrict__ bv,
    const float* __restrict__ Wout)
{
    const int tid = threadIdx.x;
    if (tid < 32) {
        const int j = tid;
        float p[16];
#pragma unroll
        for (int k = 0; k < 16; k++) p[k] = 0.f;
        for (int h = 0; h < HEADS; h++)
            for (int d = 0; d < 32; d++) {
                const int c = h * 32 + d;
                const float w = Wout[c * HIDDEN + j];
                p[h*4+0] = fmaf(Wv[c],          w, p[h*4+0]);
                p[h*4+1] = fmaf(Wv[PROJ + c],   w, p[h*4+1]);
                p[h*4+2] = fmaf(Wv[2*PROJ + c], w, p[h*4+2]);
                p[h*4+3] = fmaf(bv[c],          w, p[h*4+3]);
            }
#pragma unroll
        for (int k = 0; k < 16; k++) g_PJ[j * 16 + k] = p[k];
    } else if (tid < 68) {                       // M[h][i][jj]
        const int t = tid - 32, h = t / 9, ij = t % 9, i = ij / 3, jj = ij % 3;
        float s = 0.f;
        for (int d = 0; d < 32; d++) {
            const int c = h * 32 + d;
            s = fmaf(Wq[i * PROJ + c], Wk[jj * PROJ + c], s);
        }
        g_score[h * 13 + ij] = s;
    } else if (tid < 80) {                       // L[h][i]
        const int t = tid - 68, h = t / 3, i = t % 3;
        float s = 0.f;
        for (int d = 0; d < 32; d++) {
            const int c = h * 32 + d;
            s += Wq[i * PROJ + c] * bk[c] + bq[c] * Wk[i * PROJ + c];
        }
        g_score[h * 13 + 9 + i] = s;
    } else if (tid < 84) {                       // C[h]
        const int h = tid - 80;
        float s = 0.f;
        for (int d = 0; d < 32; d++) {
            const int c = h * 32 + d;
            s = fmaf(bq[c], bk[c], s);
        }
        g_score[h * 13 + 12] = s;
    }
}

// ---------------------------------------------------------------------------
// Zero the 6.4 MB accumulator.
// ---------------------------------------------------------------------------
__global__ __launch_bounds__(256) void zero_kernel() {
    const size_t n4 = ((size_t)N_NODES * 16) / 4;
    float4* a4 = reinterpret_cast<float4*>(g_acc);
    const size_t stride = (size_t)gridDim.x * blockDim.x;
    for (size_t i = (size_t)blockIdx.x * blockDim.x + threadIdx.x; i < n4; i += stride)
        a4[i] = make_float4(0.f, 0.f, 0.f, 0.f);
}

// ---------------------------------------------------------------------------
// Edge kernel: one thread per edge. Quadratic-form scores, 4-way softmax in
// registers, 4x red.v4.f32 (16 floats) per edge.
// ---------------------------------------------------------------------------
__global__ __launch_bounds__(256) void edge_kernel(
    const float* __restrict__ pos, const void* __restrict__ eidx_raw)
{
    __shared__ float sc[HEADS * 13];
    const int tid = threadIdx.x;
    if (tid < HEADS * 13) sc[tid] = g_score[tid];
    __syncthreads();

    const int e = blockIdx.x * 256 + tid;
    if (e >= N_EDGES) return;

    int row, col;
    if (g_idx64) {
        const long long* e64 = (const long long*)eidx_raw;
        row = (int)e64[e];
        col = (int)e64[N_EDGES + e];
    } else {
        const int* e32 = (const int*)eidx_raw;
        row = e32[e];
        col = e32[N_EDGES + e];
    }
    if ((unsigned)row >= N_NODES || (unsigned)col >= N_NODES) return;

    const float rx = pos[row * 3 + 0] - pos[col * 3 + 0];
    const float ry = pos[row * 3 + 1] - pos[col * 3 + 1];
    const float rz = pos[row * 3 + 2] - pos[col * 3 + 2];

    float s[HEADS];
#pragma unroll
    for (int h = 0; h < HEADS; h++) {
        const float* m = &sc[h * 13];
        const float tx = fmaf(m[0], rx, fmaf(m[1], ry, m[2] * rz));
        const float ty = fmaf(m[3], rx, fmaf(m[4], ry, m[5] * rz));
        const float tz = fmaf(m[6], rx, fmaf(m[7], ry, m[8] * rz));
        float v = fmaf(rx, tx, fmaf(ry, ty, rz * tz));
        v += fmaf(m[9], rx, fmaf(m[10], ry, fmaf(m[11], rz, m[12])));
        s[h] = v * 0.17677669529663687f;  // 1/sqrt(32)
    }
    float mx = fmaxf(fmaxf(s[0], s[1]), fmaxf(s[2], s[3]));
    float ex[HEADS], tot = 0.f;
#pragma unroll
    for (int h = 0; h < HEADS; h++) { ex[h] = __expf(s[h] - mx); tot += ex[h]; }
    const float inv = 1.f / tot;

    float* dst = g_acc + (size_t)col * 16;
#pragma unroll
    for (int h = 0; h < HEADS; h++) {
        const float a = ex[h] * inv;
        asm volatile("red.global.add.v4.f32 [%0], {%1,%2,%3,%4};"
                     :: "l"(dst + h * 4), "f"(a * rx), "f"(a * ry), "f"(a * rz), "f"(a)
                     : "memory");
    }
}

// ---------------------------------------------------------------------------
// Node kernel: one THREAD per node. 16-float load, 32 outputs via folded
// tables (4x LDS.128 + 16 FMA each), in-register LayerNorm + SiLU.
// ---------------------------------------------------------------------------
__global__ __launch_bounds__(256) void node_kernel(
    const float* __restrict__ bout, const float* __restrict__ gamma,
    const float* __restrict__ beta, float* __restrict__ out)
{
    __shared__ float sPJ[HIDDEN * 16];
    __shared__ float sb[HIDDEN], sg[HIDDEN], sbt[HIDDEN];
    const int tid = threadIdx.x;
    for (int i = tid; i < HIDDEN * 16; i += 256) sPJ[i] = g_PJ[i];
    if (tid < HIDDEN) { sb[tid] = bout[tid]; sg[tid] = gamma[tid]; sbt[tid] = beta[tid]; }
    __syncthreads();

    const int node = blockIdx.x * 256 + tid;
    if (node >= N_NODES) return;

    const float4* ap = reinterpret_cast<const float4*>(g_acc + (size_t)node * 16);
    const float4 a0 = ap[0], a1 = ap[1], a2 = ap[2], a3 = ap[3];
    const float cnt = a0.w + a1.w + a2.w + a3.w;
    const float inv = 1.f / fmaxf(cnt, 1.f);

    float o[HIDDEN];
    float sum = 0.f;
#pragma unroll
    for (int j = 0; j < HIDDEN; j++) {
        const float4* p = reinterpret_cast<const float4*>(&sPJ[j * 16]);
        const float4 p0 = p[0], p1 = p[1], p2 = p[2], p3 = p[3];
        float d = a0.x * p0.x + a0.y * p0.y + a0.z * p0.z + a0.w * p0.w;
        d += a1.x * p1.x + a1.y * p1.y + a1.z * p1.z + a1.w * p1.w;
        d += a2.x * p2.x + a2.y * p2.y + a2.z * p2.z + a2.w * p2.w;
        d += a3.x * p3.x + a3.y * p3.y + a3.z * p3.z + a3.w * p3.w;
        o[j] = fmaf(d, inv, sb[j]);
        sum += o[j];
    }
    const float mu = sum * (1.f / 32.f);
    float sq = 0.f;
#pragma unroll
    for (int j = 0; j < HIDDEN; j++) { const float d = o[j] - mu; sq += d * d; }
    const float rstd = rsqrtf(sq * (1.f / 32.f) + LN_EPS);

    float4 w[8];
#pragma unroll
    for (int j = 0; j < HIDDEN; j++) {
        const float y = (o[j] - mu) * rstd * sg[j] + sbt[j];
        const float r = y / (1.f + __expf(-y));
        reinterpret_cast<float*>(w)[j] = r;
    }
    float4* op = reinterpret_cast<float4*>(out + (size_t)node * HIDDEN);
#pragma unroll
    for (int k = 0; k < 8; k++) op[k] = w[k];
}

// ---------------------------------------------------------------------------
extern "C" void kernel_launch(void* const* d_in, const int* in_sizes, int n_in,
                              void* d_out, int out_size)
{
    const float* pos   = (const float*)d_in[0];
    const void*  eidx  = d_in[1];
    const float* Wq    = (const float*)d_in[2];
    const float* bq    = (const float*)d_in[3];
    const float* Wk    = (const float*)d_in[4];
    const float* bk    = (const float*)d_in[5];
    const float* Wv    = (const float*)d_in[6];
    const float* bv    = (const float*)d_in[7];
    const float* Wout  = (const float*)d_in[8];
    const float* bout  = (const float*)d_in[9];
    const float* gamma = (const float*)d_in[10];
    const float* beta  = (const float*)d_in[11];
    float*       out   = (float*)d_out;

    sniff_kernel<<<1, 32>>>((const int*)eidx);
    precompute_kernel<<<1, 128>>>(Wq, bq, Wk, bk, Wv, bv, Wout);
    zero_kernel<<<512, 256>>>();
    edge_kernel<<<(N_EDGES + 255) / 256, 256>>>(pos, eidx);
    node_kernel<<<(N_NODES + 255) / 256, 256>>>(bout, gamma, beta, out);
}